// round 11
// baseline (speedup 1.0000x reference)
#include <cuda_runtime.h>
#include <cstdint>

#define B_   64
#define A_   1024
#define D_   5
#define F_   256
#define NB_  6
#define O_   256
#define K_   262
#define TM   64
#define NTHR 256
#define CHK  32
#define NC   9            // 8 chunks of 32 + 1 bonds chunk of 6
#define ROWS_TOTAL (B_ * A_)
#define NTILES (ROWS_TOTAL / TM)
#define WSTRIDE (K_ * O_)

typedef unsigned long long ull;

__device__ int g_cnt[8];          // statically zero; reset by last CTA each call
__device__ int g_done;
__device__ int g_lists[6][ROWS_TOTAL];

__device__ __forceinline__ ull pack2(float x) {
    ull r; asm("mov.b64 %0, {%1, %1};" : "=l"(r) : "f"(x)); return r;
}
__device__ __forceinline__ void fma2(ull& a, ull x, ull y) {
    asm("fma.rn.f32x2 %0, %1, %2, %0;" : "+l"(a) : "l"(x), "l"(y));
}
__device__ __forceinline__ float sigf(float z) {
    return __fdividef(1.f, 1.f + __expf(-z));
}

__global__ void classify_kernel(const int* __restrict__ edges) {
    int rid = blockIdx.x * blockDim.x + threadIdx.x;
    const int* e = edges + (size_t)rid * D_;
    int d = 0;
    #pragma unroll
    for (int j = 0; j < D_; j++) d += (e[j] >= 0);
    unsigned lt = (1u << (threadIdx.x & 31)) - 1u;
    #pragma unroll
    for (int dd = 0; dd < 6; dd++) {
        unsigned m = __ballot_sync(0xffffffffu, d == dd);
        if (d == dd) {
            int leader = __ffs(m) - 1;
            int base = 0;
            if ((int)(threadIdx.x & 31) == leader) base = atomicAdd(&g_cnt[dd], __popc(m));
            base = __shfl_sync(m, base, leader);
            g_lists[dd][base + __popc(m & lt)] = rid;
        }
    }
}

// ---- build one 32-k chunk of the transposed feats tile (swizzled, conflict-free) ----
__device__ __forceinline__ void build_chunk(float* __restrict__ dst, int c,
                                            const float* __restrict__ atoms,
                                            const float* __restrict__ bonds,
                                            const int* __restrict__ rid_s,
                                            const int* __restrict__ edg_s) {
    const int tid = threadIdx.x;
    if (c < 8) {
        const float4* a4 = (const float4*)atoms;
        #pragma unroll
        for (int it = 0; it < 2; it++) {
            int job = it * NTHR + tid;
            int r = job >> 3, c4 = job & 7;     // r 0..63, c4 0..7 (k' = 4c4..4c4+3)
            int rid = rid_s[r];
            int cg = c * 8 + c4;
            float4 v = a4[(size_t)rid * 64 + cg];
            int bbase = rid & ~(A_ - 1);
            #pragma unroll
            for (int j = 0; j < D_; j++) {
                int e = edg_s[r * D_ + j];
                if (e >= 0) {
                    float4 n = a4[(size_t)(bbase + e) * 64 + cg];
                    v.x += n.x; v.y += n.y; v.z += n.z; v.w += n.w;
                }
            }
            int p = (r >> 2) ^ c4;
            int base = (4 * c4) * 64 + 4 * p + (r & 3);
            dst[base + 0 * 64] = v.x;
            dst[base + 1 * 64] = v.y;
            dst[base + 2 * 64] = v.z;
            dst[base + 3 * 64] = v.w;
        }
    } else {
        #pragma unroll
        for (int it = 0; it < 2; it++) {
            int job = it * NTHR + tid;
            int r = job >> 3, c4 = job & 7;
            if (c4 < 2) {
                const float* bb = bonds + (size_t)rid_s[r] * (D_ * NB_);
                #pragma unroll
                for (int q = 0; q < 4; q++) {
                    int nb = 4 * c4 + q;
                    if (nb < NB_) {
                        float s = 0.f;
                        #pragma unroll
                        for (int j = 0; j < D_; j++) s += bb[j * NB_ + nb];
                        int p = (r >> 2) ^ (nb >> 2);
                        dst[nb * 64 + 4 * p + (r & 3)] = s;
                    }
                }
            }
        }
    }
}

// ---- GEMV over one chunk: 16 rows x 4 cols per thread (R5 rolled form) ----
template <int NK>
__device__ __forceinline__ void gemv_chunk(const float* __restrict__ fb,
                                           const float* __restrict__ wk,
                                           int h, ull acc[8][4]) {
    #pragma unroll
    for (int k4 = 0; k4 < (NK + 3) / 4; k4++) {
        const int sk = k4;
        int of0 = 4 * ((4 * h + 0) ^ sk);
        int of1 = 4 * ((4 * h + 1) ^ sk);
        int of2 = 4 * ((4 * h + 2) ^ sk);
        int of3 = 4 * ((4 * h + 3) ^ sk);
        const float* f0 = fb + k4 * 4 * 64;
        const int jmax = (NK - 4 * k4 < 4) ? (NK - 4 * k4) : 4;
        #pragma unroll
        for (int j = 0; j < jmax; j++) {
            float4 w = *(const float4*)(wk + (size_t)(4 * k4 + j) * O_);
            ull wx = pack2(w.x), wy = pack2(w.y), wz = pack2(w.z), ww = pack2(w.w);
            const float* fj = f0 + j * 64;
            ulonglong2 fa = *(const ulonglong2*)(fj + of0);
            ulonglong2 fb2 = *(const ulonglong2*)(fj + of1);
            ulonglong2 fc = *(const ulonglong2*)(fj + of2);
            ulonglong2 fd = *(const ulonglong2*)(fj + of3);
            fma2(acc[0][0], fa.x, wx); fma2(acc[0][1], fa.x, wy); fma2(acc[0][2], fa.x, wz); fma2(acc[0][3], fa.x, ww);
            fma2(acc[1][0], fa.y, wx); fma2(acc[1][1], fa.y, wy); fma2(acc[1][2], fa.y, wz); fma2(acc[1][3], fa.y, ww);
            fma2(acc[2][0], fb2.x, wx); fma2(acc[2][1], fb2.x, wy); fma2(acc[2][2], fb2.x, wz); fma2(acc[2][3], fb2.x, ww);
            fma2(acc[3][0], fb2.y, wx); fma2(acc[3][1], fb2.y, wy); fma2(acc[3][2], fb2.y, wz); fma2(acc[3][3], fb2.y, ww);
            fma2(acc[4][0], fc.x, wx); fma2(acc[4][1], fc.x, wy); fma2(acc[4][2], fc.x, wz); fma2(acc[4][3], fc.x, ww);
            fma2(acc[5][0], fc.y, wx); fma2(acc[5][1], fc.y, wy); fma2(acc[5][2], fc.y, wz); fma2(acc[5][3], fc.y, ww);
            fma2(acc[6][0], fd.x, wx); fma2(acc[6][1], fd.x, wy); fma2(acc[6][2], fd.x, wz); fma2(acc[6][3], fd.x, ww);
            fma2(acc[7][0], fd.y, wx); fma2(acc[7][1], fd.y, wy); fma2(acc[7][2], fd.y, wz); fma2(acc[7][3], fd.y, ww);
        }
    }
}

__global__ void __launch_bounds__(NTHR, 3)
nfp_gemm(const float* __restrict__ atoms,
         const float* __restrict__ bonds,
         const int*   __restrict__ edges,
         const float* __restrict__ degW,
         const float* __restrict__ bias,
         float*       __restrict__ out)
{
    __shared__ __align__(16) float fbuf[2][CHK * 64];   // 2 x 8KB
    __shared__ int      rid_s[TM];
    __shared__ int      deg_s[TM];
    __shared__ int      edg_s[TM * D_];
    __shared__ unsigned pres_s;

    const int tid = threadIdx.x;
    if (tid == 0) pres_s = 0u;
    __syncthreads();

    // ---- map tile slots -> bucketed rows ----
    if (tid < TM) {
        int s = blockIdx.x * TM + tid;
        int accc = 0, d = 0, idx = 0;
        #pragma unroll
        for (int dd = 0; dd < 6; dd++) {
            int c = g_cnt[dd];
            if (s >= accc && s < accc + c) { d = dd; idx = s - accc; }
            accc += c;
        }
        int rid = g_lists[d][idx];
        rid_s[tid] = rid;
        deg_s[tid] = d;
        atomicOr(&pres_s, 1u << d);
        const int* e = edges + (size_t)rid * D_;
        #pragma unroll
        for (int j = 0; j < D_; j++) edg_s[tid * D_ + j] = e[j];
    }
    __syncthreads();

    const int c4col = tid & 63;          // cols 4*c4col .. 4*c4col+3
    const int h     = tid >> 6;          // rows 16h .. 16h+15
    const float4 bo = ((const float4*)bias)[c4col];
    const unsigned pres = pres_s;

    for (int d = 0; d < 6; d++) {
        if (!((pres >> d) & 1u)) continue;       // uniform branch

        const float* wbase = degW + (size_t)d * WSTRIDE + 4 * c4col;

        ull acc[8][4];
        #pragma unroll
        for (int q = 0; q < 8; q++)
            #pragma unroll
            for (int cc = 0; cc < 4; cc++) acc[q][cc] = 0ull;

        build_chunk(fbuf[0], 0, atoms, bonds, rid_s, edg_s);
        __syncthreads();

        #pragma unroll 1
        for (int c = 0; c < NC; c++) {
            if (c + 1 < NC)
                build_chunk(fbuf[(c + 1) & 1], c + 1, atoms, bonds, rid_s, edg_s);
            const float* wk = wbase + (size_t)(c * CHK) * O_;
            if (c < 8) gemv_chunk<32>(fbuf[c & 1], wk, h, acc);
            else       gemv_chunk<6>(fbuf[c & 1], wk, h, acc);
            __syncthreads();
        }

        // epilogue: rows r0 = 16h + 4*(q>>1) + 2*(q&1), r0+1
        #pragma unroll
        for (int q = 0; q < 8; q++) {
            int r0 = 16 * h + 4 * (q >> 1) + 2 * (q & 1);
            int r1 = r0 + 1;
            float lo[4], hi[4];
            #pragma unroll
            for (int cc = 0; cc < 4; cc++) {
                asm("mov.b64 {%0, %1}, %2;" : "=f"(lo[cc]), "=f"(hi[cc]) : "l"(acc[q][cc]));
            }
            if (deg_s[r0] == d) {
                float4 v = make_float4(sigf(lo[0] + bo.x), sigf(lo[1] + bo.y),
                                       sigf(lo[2] + bo.z), sigf(lo[3] + bo.w));
                *(float4*)(out + (size_t)rid_s[r0] * O_ + 4 * c4col) = v;
            }
            if (deg_s[r1] == d) {
                float4 v = make_float4(sigf(hi[0] + bo.x), sigf(hi[1] + bo.y),
                                       sigf(hi[2] + bo.z), sigf(hi[3] + bo.w));
                *(float4*)(out + (size_t)rid_s[r1] * O_ + 4 * c4col) = v;
            }
        }
    }

    // ---- self-resetting state for the next call (replaces zero_kernel) ----
    __syncthreads();
    if (tid == 0) {
        int v = atomicAdd(&g_done, 1);
        if (v == NTILES - 1) {
            #pragma unroll
            for (int i = 0; i < 8; i++) g_cnt[i] = 0;
            g_done = 0;
            __threadfence();
        }
    }
}

extern "C" void kernel_launch(void* const* d_in, const int* in_sizes, int n_in,
                              void* d_out, int out_size) {
    const float* atoms = (const float*)d_in[0];
    const float* bonds = (const float*)d_in[1];
    const int*   edges = (const int*)d_in[2];
    const float* degW  = (const float*)d_in[3];
    const float* bvec  = (const float*)d_in[4];
    float* out = (float*)d_out;

    classify_kernel<<<ROWS_TOTAL / 256, 256>>>(edges);
    nfp_gemm<<<NTILES, NTHR>>>(atoms, bonds, edges, degW, bvec, out);
}

// round 12
// speedup vs baseline: 3.7880x; 3.7880x over previous
#include <cuda_runtime.h>
#include <cstdint>

#define B_   64
#define A_   1024
#define D_   5
#define F_   256
#define NB_  6
#define O_   256
#define K_   262
#define TM   64
#define NTHR 256
#define CHK  32
#define NC   9            // 8 chunks of 32 + 1 bonds chunk of 6
#define ROWS_TOTAL (B_ * A_)
#define NTILES (ROWS_TOTAL / TM)
#define WSTRIDE (K_ * O_)

typedef unsigned long long ull;

__device__ int g_cnt[8];          // statically zero; reset by last CTA each call
__device__ int g_done;
__device__ int g_lists[6][ROWS_TOTAL];

__device__ __forceinline__ ull pack2(float x) {
    ull r; asm("mov.b64 %0, {%1, %1};" : "=l"(r) : "f"(x)); return r;
}
__device__ __forceinline__ void fma2(ull& a, ull x, ull y) {
    asm("fma.rn.f32x2 %0, %1, %2, %0;" : "+l"(a) : "l"(x), "l"(y));
}
__device__ __forceinline__ float sigf(float z) {
    return __fdividef(1.f, 1.f + __expf(-z));
}

__global__ void classify_kernel(const int* __restrict__ edges) {
    int rid = blockIdx.x * blockDim.x + threadIdx.x;
    const int* e = edges + (size_t)rid * D_;
    int d = 0;
    #pragma unroll
    for (int j = 0; j < D_; j++) d += (e[j] >= 0);
    unsigned lt = (1u << (threadIdx.x & 31)) - 1u;
    #pragma unroll
    for (int dd = 0; dd < 6; dd++) {
        unsigned m = __ballot_sync(0xffffffffu, d == dd);
        if (d == dd) {
            int leader = __ffs(m) - 1;
            int base = 0;
            if ((int)(threadIdx.x & 31) == leader) base = atomicAdd(&g_cnt[dd], __popc(m));
            base = __shfl_sync(m, base, leader);
            g_lists[dd][base + __popc(m & lt)] = rid;
        }
    }
}

// ---- build one 32-k chunk of the transposed feats tile (swizzled, conflict-free) ----
__device__ __forceinline__ void build_chunk(float* __restrict__ dst, int c,
                                            const float* __restrict__ atoms,
                                            const float* __restrict__ bonds,
                                            const int* __restrict__ rid_s,
                                            const int* __restrict__ edg_s) {
    const int tid = threadIdx.x;
    if (c < 8) {
        const float4* a4 = (const float4*)atoms;
        #pragma unroll
        for (int it = 0; it < 2; it++) {
            int job = it * NTHR + tid;
            int r = job >> 3, c4 = job & 7;     // r 0..63, c4 0..7 (k' = 4c4..4c4+3)
            int rid = rid_s[r];
            int cg = c * 8 + c4;
            float4 v = a4[(size_t)rid * 64 + cg];
            int bbase = rid & ~(A_ - 1);
            #pragma unroll
            for (int j = 0; j < D_; j++) {
                int e = edg_s[r * D_ + j];
                if (e >= 0) {
                    float4 n = a4[(size_t)(bbase + e) * 64 + cg];
                    v.x += n.x; v.y += n.y; v.z += n.z; v.w += n.w;
                }
            }
            int p = (r >> 2) ^ c4;
            int base = (4 * c4) * 64 + 4 * p + (r & 3);
            dst[base + 0 * 64] = v.x;
            dst[base + 1 * 64] = v.y;
            dst[base + 2 * 64] = v.z;
            dst[base + 3 * 64] = v.w;
        }
    } else {
        #pragma unroll
        for (int it = 0; it < 2; it++) {
            int job = it * NTHR + tid;
            int r = job >> 3, c4 = job & 7;
            if (c4 < 2) {
                const float* bb = bonds + (size_t)rid_s[r] * (D_ * NB_);
                #pragma unroll
                for (int q = 0; q < 4; q++) {
                    int nb = 4 * c4 + q;
                    if (nb < NB_) {
                        float s = 0.f;
                        #pragma unroll
                        for (int j = 0; j < D_; j++) s += bb[j * NB_ + nb];
                        int p = (r >> 2) ^ (nb >> 2);
                        dst[nb * 64 + 4 * p + (r & 3)] = s;
                    }
                }
            }
        }
    }
}

// ---- GEMV over one chunk: 16 rows x 4 cols per thread (R5 rolled form) ----
template <int NK>
__device__ __forceinline__ void gemv_chunk(const float* __restrict__ fb,
                                           const float* __restrict__ wk,
                                           int h, ull acc[8][4]) {
    #pragma unroll
    for (int k4 = 0; k4 < (NK + 3) / 4; k4++) {
        const int sk = k4;
        int of0 = 4 * ((4 * h + 0) ^ sk);
        int of1 = 4 * ((4 * h + 1) ^ sk);
        int of2 = 4 * ((4 * h + 2) ^ sk);
        int of3 = 4 * ((4 * h + 3) ^ sk);
        const float* f0 = fb + k4 * 4 * 64;
        const int jmax = (NK - 4 * k4 < 4) ? (NK - 4 * k4) : 4;
        #pragma unroll
        for (int j = 0; j < jmax; j++) {
            float4 w = *(const float4*)(wk + (size_t)(4 * k4 + j) * O_);
            ull wx = pack2(w.x), wy = pack2(w.y), wz = pack2(w.z), ww = pack2(w.w);
            const float* fj = f0 + j * 64;
            ulonglong2 fa = *(const ulonglong2*)(fj + of0);
            ulonglong2 fb2 = *(const ulonglong2*)(fj + of1);
            ulonglong2 fc = *(const ulonglong2*)(fj + of2);
            ulonglong2 fd = *(const ulonglong2*)(fj + of3);
            fma2(acc[0][0], fa.x, wx); fma2(acc[0][1], fa.x, wy); fma2(acc[0][2], fa.x, wz); fma2(acc[0][3], fa.x, ww);
            fma2(acc[1][0], fa.y, wx); fma2(acc[1][1], fa.y, wy); fma2(acc[1][2], fa.y, wz); fma2(acc[1][3], fa.y, ww);
            fma2(acc[2][0], fb2.x, wx); fma2(acc[2][1], fb2.x, wy); fma2(acc[2][2], fb2.x, wz); fma2(acc[2][3], fb2.x, ww);
            fma2(acc[3][0], fb2.y, wx); fma2(acc[3][1], fb2.y, wy); fma2(acc[3][2], fb2.y, wz); fma2(acc[3][3], fb2.y, ww);
            fma2(acc[4][0], fc.x, wx); fma2(acc[4][1], fc.x, wy); fma2(acc[4][2], fc.x, wz); fma2(acc[4][3], fc.x, ww);
            fma2(acc[5][0], fc.y, wx); fma2(acc[5][1], fc.y, wy); fma2(acc[5][2], fc.y, wz); fma2(acc[5][3], fc.y, ww);
            fma2(acc[6][0], fd.x, wx); fma2(acc[6][1], fd.x, wy); fma2(acc[6][2], fd.x, wz); fma2(acc[6][3], fd.x, ww);
            fma2(acc[7][0], fd.y, wx); fma2(acc[7][1], fd.y, wy); fma2(acc[7][2], fd.y, wz); fma2(acc[7][3], fd.y, ww);
        }
    }
}

__global__ void __launch_bounds__(NTHR, 2)
nfp_gemm(const float* __restrict__ atoms,
         const float* __restrict__ bonds,
         const int*   __restrict__ edges,
         const float* __restrict__ degW,
         const float* __restrict__ bias,
         float*       __restrict__ out)
{
    __shared__ __align__(16) float fbuf[2][CHK * 64];   // 2 x 8KB
    __shared__ int      rid_s[TM];
    __shared__ int      deg_s[TM];
    __shared__ int      edg_s[TM * D_];
    __shared__ unsigned pres_s;

    const int tid = threadIdx.x;
    if (tid == 0) pres_s = 0u;
    __syncthreads();

    // ---- map tile slots -> bucketed rows ----
    if (tid < TM) {
        int s = blockIdx.x * TM + tid;
        int accc = 0, d = 0, idx = 0;
        #pragma unroll
        for (int dd = 0; dd < 6; dd++) {
            int c = g_cnt[dd];
            if (s >= accc && s < accc + c) { d = dd; idx = s - accc; }
            accc += c;
        }
        int rid = g_lists[d][idx];
        rid_s[tid] = rid;
        deg_s[tid] = d;
        atomicOr(&pres_s, 1u << d);
        const int* e = edges + (size_t)rid * D_;
        #pragma unroll
        for (int j = 0; j < D_; j++) edg_s[tid * D_ + j] = e[j];
    }
    __syncthreads();

    const int c4col = tid & 63;          // cols 4*c4col .. 4*c4col+3
    const int h     = tid >> 6;          // rows 16h .. 16h+15
    const float4 bo = ((const float4*)bias)[c4col];
    const unsigned pres = pres_s;

    for (int d = 0; d < 6; d++) {
        if (!((pres >> d) & 1u)) continue;       // uniform branch

        const float* wbase = degW + (size_t)d * WSTRIDE + 4 * c4col;

        ull acc[8][4];
        #pragma unroll
        for (int q = 0; q < 8; q++)
            #pragma unroll
            for (int cc = 0; cc < 4; cc++) acc[q][cc] = 0ull;

        build_chunk(fbuf[0], 0, atoms, bonds, rid_s, edg_s);
        __syncthreads();

        #pragma unroll 1
        for (int c = 0; c < NC; c++) {
            if (c + 1 < NC)
                build_chunk(fbuf[(c + 1) & 1], c + 1, atoms, bonds, rid_s, edg_s);
            const float* wk = wbase + (size_t)(c * CHK) * O_;
            if (c < 8) gemv_chunk<32>(fbuf[c & 1], wk, h, acc);
            else       gemv_chunk<6>(fbuf[c & 1], wk, h, acc);
            __syncthreads();
        }

        // epilogue: rows r0 = 16h + 4*(q>>1) + 2*(q&1), r0+1
        #pragma unroll
        for (int q = 0; q < 8; q++) {
            int r0 = 16 * h + 4 * (q >> 1) + 2 * (q & 1);
            int r1 = r0 + 1;
            float lo[4], hi[4];
            #pragma unroll
            for (int cc = 0; cc < 4; cc++) {
                asm("mov.b64 {%0, %1}, %2;" : "=f"(lo[cc]), "=f"(hi[cc]) : "l"(acc[q][cc]));
            }
            if (deg_s[r0] == d) {
                float4 v = make_float4(sigf(lo[0] + bo.x), sigf(lo[1] + bo.y),
                                       sigf(lo[2] + bo.z), sigf(lo[3] + bo.w));
                *(float4*)(out + (size_t)rid_s[r0] * O_ + 4 * c4col) = v;
            }
            if (deg_s[r1] == d) {
                float4 v = make_float4(sigf(hi[0] + bo.x), sigf(hi[1] + bo.y),
                                       sigf(hi[2] + bo.z), sigf(hi[3] + bo.w));
                *(float4*)(out + (size_t)rid_s[r1] * O_ + 4 * c4col) = v;
            }
        }
    }

    // ---- self-resetting state for the next call (replaces zero_kernel) ----
    __syncthreads();
    if (tid == 0) {
        int v = atomicAdd(&g_done, 1);
        if (v == NTILES - 1) {
            #pragma unroll
            for (int i = 0; i < 8; i++) g_cnt[i] = 0;
            g_done = 0;
            __threadfence();
        }
    }
}

extern "C" void kernel_launch(void* const* d_in, const int* in_sizes, int n_in,
                              void* d_out, int out_size) {
    const float* atoms = (const float*)d_in[0];
    const float* bonds = (const float*)d_in[1];
    const int*   edges = (const int*)d_in[2];
    const float* degW  = (const float*)d_in[3];
    const float* bvec  = (const float*)d_in[4];
    float* out = (float*)d_out;

    classify_kernel<<<ROWS_TOTAL / 256, 256>>>(edges);
    nfp_gemm<<<NTILES, NTHR>>>(atoms, bonds, edges, degW, bvec, out);
}